// round 16
// baseline (speedup 1.0000x reference)
#include <cuda_runtime.h>
#include <cuda_fp16.h>
#include <cstdint>
#include <math.h>

#define ID 56
#define OD 52
#define NSITE (ID*ID*ID)           // 175616
#define OSZ (OD*OD*OD)             // 140608
#define PLANE (8*56*64)            // 28672 B: one z-plane (8y x 56x x 64B)
#define NPLANE 6
#define WINB (NPLANE*PLANE)        // 172032
#define SLABB 20480                // 5 taps x 64o x 64B
#define NRING 2
#define CTRL 512
#define SMEMB (CTRL + WINB + NRING*SLABB)   // 213504
#define XCHB (NSITE*64)            // bytes per x chunk
#define WCHB 512000                // bytes per weight chunk
#define WCHH 256000                // halves per weight chunk

__device__ __align__(1024) __half g_xh[2u*NSITE*32];   // [chunk][site][32c] SW64-swizzled
__device__ __align__(1024) __half g_Wh[2u*125*64*32];  // [chunk][tap][o][32c] SW64-swizzled

__device__ __forceinline__ uint32_t swz(uint32_t a){ return a ^ ((a>>3)&0x30u); }
__device__ __forceinline__ uint32_t s2u(const void* p){
    uint32_t a; asm("{ .reg .u64 t; cvta.to.shared.u64 t, %1; cvt.u32.u64 %0, t; }":"=r"(a):"l"(p)); return a;
}
#define MBAR_INIT(a,c) asm volatile("mbarrier.init.shared.b64 [%0], %1;"::"r"(a),"r"(c):"memory")
#define MBAR_TX(a,b)   asm volatile("mbarrier.arrive.expect_tx.shared.b64 _, [%0], %1;"::"r"(a),"r"(b):"memory")
#define MBAR_WAIT(a,p) do{ uint32_t _m=(a),_p=(p); asm volatile( \
    "{\n\t.reg .pred P;\n\tW%=:\n\t" \
    "mbarrier.try_wait.parity.acquire.cta.shared::cta.b64 P, [%0], %1, 0x989680;\n\t" \
    "@P bra.uni D%=;\n\tbra.uni W%=;\n\tD%=:\n\t}"::"r"(_m),"r"(_p):"memory"); }while(0)
#define BULK(dst,src,n,mb) asm volatile( \
    "cp.async.bulk.shared::cluster.global.mbarrier::complete_tx::bytes [%0], [%1], %2, [%3];" \
    ::"r"(dst),"l"(src),"r"(n),"r"(mb):"memory")
#define LDSM_X4(r, a) asm volatile( \
    "ldmatrix.sync.aligned.m8n8.x4.shared.b16 {%0,%1,%2,%3}, [%4];" \
    : "=r"((r)[0]),"=r"((r)[1]),"=r"((r)[2]),"=r"((r)[3]) : "r"(a))
#define MMA16816(d, a, b) asm volatile( \
    "mma.sync.aligned.m16n8k16.row.col.f32.f16.f16.f32 " \
    "{%0,%1,%2,%3}, {%4,%5,%6,%7}, {%8,%9}, {%0,%1,%2,%3};" \
    : "+f"((d)[0]),"+f"((d)[1]),"+f"((d)[2]),"+f"((d)[3]) \
    : "r"((a)[0]),"r"((a)[1]),"r"((a)[2]),"r"((a)[3]), "r"((b)[0]),"r"((b)[1]))

// ---------------- prep: weights -> fp16 swizzled [chunk][tap][o64][c32] ----
__global__ void build_w(const float* __restrict__ weight,
                        const float* __restrict__ w_sc0,
                        const float* __restrict__ w_sc1){
    const int tap = blockIdx.x;
    const int i = tap/25, j = (tap/5)%5, k = tap%5;
    const float rr[5] = {-1.f,-0.5f,0.f,0.5f,1.f};
    const float ri=rr[i], rj=rr[j], rk=rr[k];
    const float d = sqrtf(ri*ri+rj*rj+rk*rk);
    float emb[5]; const float C = 1.14136f*7.389056098930650f;
    #pragma unroll
    for (int t=0;t<5;t++){
        float diff = 4.f*d - (float)t;
        float t1 = diff+1.f, t2 = 1.f-diff;
        float s1 = (t1>0.f)?expf(-1.f/t1):0.f;
        float s2 = (t2>0.f)?expf(-1.f/t2):0.f;
        emb[t] = C*s1*s2;
    }
    const float dn = fmaxf(d,1e-12f);
    const float SQ3 = 1.7320508075688772f;
    float sh[3] = {SQ3*ri/dn, SQ3*rj/dn, SQ3*rk/dn};
    const int tid = threadIdx.x, u = tid>>4, wc = tid&15, col = u*16+wc;
    float w1=0,w2=0,w3=0,w4=0;
    #pragma unroll
    for (int t=0;t<5;t++){
        float e = emb[t];
        w1 += e*weight[t*1024+  0+col]; w2 += e*weight[t*1024+256+col];
        w3 += e*weight[t*1024+512+col]; w4 += e*weight[t*1024+768+col];
    }
    const float PW0=0.17677669529663687f, PW1=0.30618621784789724f, IS3=0.57735026918962576f;
    const bool center = (tap==62);
    auto put = [&](int ci, int o, float v){
        int ch = ci>>5, c = ci&31;
        uint32_t byte = (uint32_t)tap*4096u + (uint32_t)o*64u + (uint32_t)c*2u;
        g_Wh[(uint32_t)ch*WCHH + swz(byte)/2] = __float2half(v);
    };
    float vss = PW0*w1; if (center) vss += 0.25f*w_sc0[u*16+wc];
    put(u, wc, vss);
    #pragma unroll
    for (int kc=0;kc<3;kc++) put(u, 16+wc*3+kc, PW1*IS3*w2*sh[kc]);
    #pragma unroll
    for (int ic=0;ic<3;ic++) put(16+u*3+ic, wc, PW0*IS3*w4*sh[ic]);
    float vv = PW1*IS3*w3; if (center) vv += 0.25f*w_sc1[u*16+wc];
    #pragma unroll
    for (int ic=0;ic<3;ic++)
        #pragma unroll
        for (int jc=0;jc<3;jc++)
            put(16+u*3+ic, 16+wc*3+jc, (ic==jc)?vv:0.f);
}

// ------------- prep: x -> fp16 swizzled [chunk][site][32c] (64B rows) ------
__global__ void __launch_bounds__(256) conv_x(const float* __restrict__ x){
    __shared__ uint32_t sb[16][514];
    const int chunk = blockIdx.y;
    const int site0 = blockIdx.x*512;
    const int tid = threadIdx.x;
    #pragma unroll
    for (int p=0;p<16;p++){
        const float* a = x + (size_t)(chunk*32+2*p)*NSITE + site0;
        const float* b = a + NSITE;
        sb[p][tid]     = ((uint32_t)__half_as_ushort(__float2half(a[tid]))) |
                         ((uint32_t)__half_as_ushort(__float2half(b[tid]))<<16);
        sb[p][tid+256] = ((uint32_t)__half_as_ushort(__float2half(a[tid+256]))) |
                         ((uint32_t)__half_as_ushort(__float2half(b[tid+256]))<<16);
    }
    __syncthreads();
    uint32_t* dst = (uint32_t*)g_xh + (uint32_t)chunk*(XCHB/4);
    #pragma unroll
    for (int it=0;it<32;it++){
        int jdx = tid + it*256;
        int sl = jdx>>4, p = jdx&15;
        uint32_t byte = (uint32_t)(site0+sl)*64u + (uint32_t)p*4u;
        dst[swz(byte)/4] = sb[p][sl];
    }
}

// ---------------------------- main HMMA conv -------------------------------
// Block: 2 z x 4 y x 56 x sites (M=448, 28 m-tiles), N=64, K=8000.
// 8 warps: warps 0-3 -> 4 m-tiles, warps 4-7 -> 3 m-tiles (SMSP-balanced 4+3).
__global__ void __launch_bounds__(256,1) conv_mma(float* __restrict__ out){
    extern __shared__ __align__(1024) char sm[];
    const uint32_t smb = s2u(sm);
    const int tid = threadIdx.x, w = tid>>5, l = tid&31;
    const uint32_t mb_win = smb;
    const uint32_t win = smb + CTRL;
    const uint32_t slabs = win + WINB;

    if (tid==0){
        MBAR_INIT(mb_win,1);
        MBAR_INIT(smb+8,1); MBAR_INIT(smb+16,1);
    }
    __syncthreads();

    const int y0 = blockIdx.x*4, z0 = blockIdx.y*2;
    const char* gW = (const char*)g_Wh;
    const char* gX = (const char*)g_xh;

    if (tid==0){
        MBAR_TX(mb_win, WINB);
        #pragma unroll
        for (int dz=0;dz<NPLANE;dz++)
            BULK(win + dz*PLANE,
                 gX + (size_t)((z0+dz)*3136 + y0*56)*64, PLANE, mb_win);
        #pragma unroll
        for (int q=0;q<NRING;q++){
            MBAR_TX(smb+8+q*8, SLABB);
            BULK(slabs + q*SLABB, gW + q*SLABB, SLABB, smb+8+q*8);
        }
    }

    // per-warp m-tiles
    const int tbase = (w<4) ? w*4 : 16 + (w-4)*3;
    const int MTn   = (w<4) ? 4 : 3;
    uint32_t soff[4];
    #pragma unroll
    for (int mt=0; mt<4; mt++){
        int s = (tbase + ((mt<MTn)?mt:0))*16 + (l&15);
        int zz = s/224, rem = s - zz*224;
        int yy = rem/56, xx = rem - yy*56;
        soff[mt] = (uint32_t)((zz*448 + yy*56 + xx)*64) + ((uint32_t)(l>>4))*16u;
    }
    const uint32_t bL = ((uint32_t)((l&7) + ((l&16)>>1)))*64u + ((uint32_t)(l&8)<<1);
    uint32_t bsw[2]; bsw[0] = swz(bL); bsw[1] = swz(bL + 32u);

    float acc[4][8][4];
    #pragma unroll
    for (int mt=0;mt<4;mt++)
        #pragma unroll
        for (int nt=0;nt<8;nt++)
            #pragma unroll
            for (int q=0;q<4;q++) acc[mt][nt][q] = 0.f;

    MBAR_WAIT(mb_win, 0);

    for (int i=0;i<50;i++){
        if (i==25) MBAR_WAIT(mb_win, 1);
        const int q = i&1;
        MBAR_WAIT(smb+8+q*8, (i>>1)&1);
        const uint32_t sl = slabs + q*SLABB;
        const int s5 = (i%25)*5;
        #pragma unroll
        for (int jt=0;jt<5;jt++){
            const int t = s5 + jt;
            const int dz = t/25, dy = (t/5)%5, dx = t%5;
            const uint32_t D = (uint32_t)((dz*448 + dy*56 + dx)*64);
            #pragma unroll
            for (int kk=0;kk<2;kk++){
                uint32_t bf[16];
                #pragma unroll
                for (int g=0; g<4; g++)
                    LDSM_X4(bf + g*4, sl + (uint32_t)jt*4096u + (uint32_t)g*1024u + bsw[kk]);
                #pragma unroll
                for (int mt=0; mt<4; mt++){
                    if (mt < MTn){
                        uint32_t af[4];
                        LDSM_X4(af, win + swz(soff[mt] + D + (uint32_t)kk*32u));
                        #pragma unroll
                        for (int nt=0; nt<8; nt++)
                            MMA16816(acc[mt][nt], af, bf + nt*2);
                    }
                }
            }
        }
        __syncthreads();
        if (tid==0){
            const int nx = i + NRING;
            if (nx < 50){
                MBAR_TX(smb+8+q*8, SLABB);
                BULK(slabs + q*SLABB,
                     gW + (size_t)(nx/25)*WCHB + (size_t)(nx%25)*SLABB,
                     SLABB, smb+8+q*8);
            }
            if (i<25 && (i%5)==4){
                if (i==4) MBAR_TX(mb_win, WINB);
                const int g = i/5;   // plane g of chunk0 is dead now
                BULK(win + g*PLANE,
                     gX + (size_t)XCHB + (size_t)((z0+g)*3136 + y0*56)*64,
                     PLANE, mb_win);
                if (i==24)           // last plane (only used by dz=4)
                    BULK(win + 5*PLANE,
                         gX + (size_t)XCHB + (size_t)((z0+5)*3136 + y0*56)*64,
                         PLANE, mb_win);
            }
        }
    }

    // ---- epilogue: scatter accs to out[c][z][y][x] ----
    #pragma unroll
    for (int mt=0; mt<4; mt++){
        if (mt < MTn){
            #pragma unroll
            for (int h=0; h<2; h++){
                const int r = (tbase+mt)*16 + (l>>2) + h*8;
                const int zz = r/224, rem = r - zz*224;
                const int yy = rem/56, xp = rem - yy*56;
                if (xp < OD){
                    const size_t sp = ((size_t)(z0+zz)*OD + (y0+yy))*OD + xp;
                    #pragma unroll
                    for (int nt=0; nt<8; nt++){
                        const int n = nt*8 + 2*(l&3);
                        out[(size_t)n*OSZ + sp]     = acc[mt][nt][h*2];
                        out[(size_t)(n+1)*OSZ + sp] = acc[mt][nt][h*2+1];
                    }
                }
            }
        }
    }
}

// ---------------------------------------------------------------------------
extern "C" void kernel_launch(void* const* d_in, const int* in_sizes, int n_in,
                              void* d_out, int out_size){
    const float* x      = (const float*)d_in[0];
    const float* weight = (const float*)d_in[1];
    const float* w_sc0  = (const float*)d_in[2];
    const float* w_sc1  = (const float*)d_in[3];
    float* out = (float*)d_out;

    build_w<<<125,256>>>(weight, w_sc0, w_sc1);
    dim3 gx(NSITE/512, 2);
    conv_x<<<gx,256>>>(x);

    cudaFuncSetAttribute(conv_mma, cudaFuncAttributeMaxDynamicSharedMemorySize, SMEMB);
    dim3 grid(13, 26);
    conv_mma<<<grid,256,SMEMB>>>(out);
}

// round 17
// speedup vs baseline: 1.5357x; 1.5357x over previous
#include <cuda_runtime.h>
#include <cuda_fp16.h>
#include <cstdint>
#include <math.h>

#define ID 56
#define OD 52
#define NSITE (ID*ID*ID)           // 175616
#define OSZ (OD*OD*OD)             // 140608
#define PL16 (8*56*32)             // 14336 B: one z-plane, 16ch group
#define WIN16 (5*PL16)             // 71680
#define SLAB1 15360                // 5 taps x 6 mats x 512B
#define SLAB2 7680                 // 5 taps x 3 mats x 512B
#define CTRL 512
#define SMEMB (CTRL + 2*WIN16 + 2*SLAB1)   // 174592
#define WPASS2 384000              // byte offset of pass2 weights

// x in fp16, channel-reordered into 4 groups [s, vx, vy, vz], 32B site rows,
// SW64-swizzled. g_xh[g][site][16c]
__device__ __align__(1024) __half g_xh[4u*NSITE*16];
// weights: pass1 [tap][W1,W2x,W2y,W2z,W4x,W3] (3072B/tap),
//          pass2 [tap][W4y,W4z,W3] (1536B/tap) at WPASS2. All swizzled.
__device__ __align__(1024) __half g_Wh[288000];

__device__ __forceinline__ uint32_t swz(uint32_t a){ return a ^ ((a>>3)&0x30u); }
__device__ __forceinline__ uint32_t s2u(const void* p){
    uint32_t a; asm("{ .reg .u64 t; cvta.to.shared.u64 t, %1; cvt.u32.u64 %0, t; }":"=r"(a):"l"(p)); return a;
}
#define MBAR_INIT(a,c) asm volatile("mbarrier.init.shared.b64 [%0], %1;"::"r"(a),"r"(c):"memory")
#define MBAR_TX(a,b)   asm volatile("mbarrier.arrive.expect_tx.shared.b64 _, [%0], %1;"::"r"(a),"r"(b):"memory")
#define MBAR_WAIT(a,p) do{ uint32_t _m=(a),_p=(p); asm volatile( \
    "{\n\t.reg .pred P;\n\tW%=:\n\t" \
    "mbarrier.try_wait.parity.acquire.cta.shared::cta.b64 P, [%0], %1, 0x989680;\n\t" \
    "@P bra.uni D%=;\n\tbra.uni W%=;\n\tD%=:\n\t}"::"r"(_m),"r"(_p):"memory"); }while(0)
#define BULK(dst,src,n,mb) asm volatile( \
    "cp.async.bulk.shared::cluster.global.mbarrier::complete_tx::bytes [%0], [%1], %2, [%3];" \
    ::"r"(dst),"l"(src),"r"(n),"r"(mb):"memory")
#define LDSM_X4(r, a) asm volatile( \
    "ldmatrix.sync.aligned.m8n8.x4.shared.b16 {%0,%1,%2,%3}, [%4];" \
    : "=r"((r)[0]),"=r"((r)[1]),"=r"((r)[2]),"=r"((r)[3]) : "r"(a))
#define MMA16816(d, a, b) asm volatile( \
    "mma.sync.aligned.m16n8k16.row.col.f32.f16.f16.f32 " \
    "{%0,%1,%2,%3}, {%4,%5,%6,%7}, {%8,%9}, {%0,%1,%2,%3};" \
    : "+f"((d)[0]),"+f"((d)[1]),"+f"((d)[2]),"+f"((d)[3]) \
    : "r"((a)[0]),"r"((a)[1]),"r"((a)[2]),"r"((a)[3]), "r"((b)[0]),"r"((b)[1]))

// ---------------- prep: weights -> component-split 16x16 mats --------------
__global__ void build_w(const float* __restrict__ weight,
                        const float* __restrict__ w_sc0,
                        const float* __restrict__ w_sc1){
    const int tap = blockIdx.x;
    const int i = tap/25, j = (tap/5)%5, k = tap%5;
    const float rr[5] = {-1.f,-0.5f,0.f,0.5f,1.f};
    const float ri=rr[i], rj=rr[j], rk=rr[k];
    const float d = sqrtf(ri*ri+rj*rj+rk*rk);
    float emb[5]; const float C = 1.14136f*7.389056098930650f;
    #pragma unroll
    for (int t=0;t<5;t++){
        float diff = 4.f*d - (float)t;
        float t1 = diff+1.f, t2 = 1.f-diff;
        float s1 = (t1>0.f)?expf(-1.f/t1):0.f;
        float s2 = (t2>0.f)?expf(-1.f/t2):0.f;
        emb[t] = C*s1*s2;
    }
    const float dn = fmaxf(d,1e-12f);
    const float SQ3 = 1.7320508075688772f;
    float sh[3] = {SQ3*ri/dn, SQ3*rj/dn, SQ3*rk/dn};
    const int tid = threadIdx.x, u = tid>>4, wc = tid&15, col = u*16+wc;
    float w1=0,w2=0,w3=0,w4=0;
    #pragma unroll
    for (int t=0;t<5;t++){
        float e = emb[t];
        w1 += e*weight[t*1024+  0+col]; w2 += e*weight[t*1024+256+col];
        w3 += e*weight[t*1024+512+col]; w4 += e*weight[t*1024+768+col];
    }
    const float PW0=0.17677669529663687f, PW1=0.30618621784789724f, IS3=0.57735026918962576f;
    const bool center = (tap==62);
    // B[n=out][k=in], mats 512B, swizzled in-place
    auto put = [&](uint32_t matbase, float v){
        g_Wh[(matbase + swz((uint32_t)wc*32u + (uint32_t)u*2u))/2] = __float2half(v);
    };
    const uint32_t p1 = (uint32_t)tap*3072u;
    const uint32_t p2 = WPASS2 + (uint32_t)tap*1536u;
    float vW1 = PW0*w1; if (center) vW1 += 0.25f*w_sc0[u*16+wc];
    float vW3 = PW1*IS3*w3; if (center) vW3 += 0.25f*w_sc1[u*16+wc];
    put(p1 +    0, vW1);                    // W1
    put(p1 +  512, PW1*IS3*w2*sh[0]);       // W2x
    put(p1 + 1024, PW1*IS3*w2*sh[1]);       // W2y
    put(p1 + 1536, PW1*IS3*w2*sh[2]);       // W2z
    put(p1 + 2048, PW0*IS3*w4*sh[0]);       // W4x
    put(p1 + 2560, vW3);                    // W3 (pass1 copy)
    put(p2 +    0, PW0*IS3*w4*sh[1]);       // W4y
    put(p2 +  512, PW0*IS3*w4*sh[2]);       // W4z
    put(p2 + 1024, vW3);                    // W3 (pass2 copy)
}

// ------- prep: x -> fp16 groups [s|vx|vy|vz][site][16c], 32B swizzled rows --
__global__ void __launch_bounds__(256) conv_x(const float* __restrict__ x){
    __shared__ uint32_t sb[8][514];
    const int g = blockIdx.y;              // channel group 0..3
    const int site0 = blockIdx.x*512;
    const int tid = threadIdx.x;
    #pragma unroll
    for (int p=0;p<8;p++){
        const int c0 = (g==0) ? 2*p   : 16 + (2*p)*3   + (g-1);
        const int c1 = (g==0) ? 2*p+1 : 16 + (2*p+1)*3 + (g-1);
        const float* A_ = x + (size_t)c0*NSITE + site0;
        const float* B_ = x + (size_t)c1*NSITE + site0;
        sb[p][tid]     = ((uint32_t)__half_as_ushort(__float2half(A_[tid]))) |
                         ((uint32_t)__half_as_ushort(__float2half(B_[tid]))<<16);
        sb[p][tid+256] = ((uint32_t)__half_as_ushort(__float2half(A_[tid+256]))) |
                         ((uint32_t)__half_as_ushort(__float2half(B_[tid+256]))<<16);
    }
    __syncthreads();
    uint32_t* dst = (uint32_t*)g_xh + (uint32_t)g*(NSITE*8);
    #pragma unroll
    for (int it=0;it<16;it++){
        int idx = tid + it*256;
        int sl = idx>>3, p = idx&7;
        uint32_t byte = (uint32_t)(site0+sl)*32u + (uint32_t)p*4u;
        dst[swz(byte)/4] = sb[p][sl];
    }
}

// ---------------------------- main HMMA conv -------------------------------
// Block: 1z x 4y x 56x (M=256, 16 m-tiles), 4 warps x mt=4. Two passes:
//   pass1: windows (s, vx): W1,W2x,W2y,W2z (from s), W4x,W3 (from vx)
//   pass2: windows (vy,vz): W4y,W3 (vy), W4z,W3 (vz)
__global__ void __launch_bounds__(128,1) conv_mma(float* __restrict__ out){
    extern __shared__ __align__(1024) char sm[];
    const uint32_t smb = s2u(sm);
    const int tid = threadIdx.x, w = tid>>5, l = tid&31;
    const uint32_t mb_win = smb;
    const uint32_t win0 = smb + CTRL;
    const uint32_t win1 = win0 + WIN16;
    const uint32_t slabs = win1 + WIN16;

    if (tid==0){ MBAR_INIT(mb_win,1); MBAR_INIT(smb+8,1); MBAR_INIT(smb+16,1); }
    __syncthreads();

    const int y0 = blockIdx.x*4, z0 = blockIdx.y;
    const char* gW = (const char*)g_Wh;
    const char* gX = (const char*)g_xh;

    if (tid==0){
        MBAR_TX(mb_win, 2u*WIN16);
        #pragma unroll
        for (int dz=0;dz<5;dz++){
            const size_t rowoff = (size_t)((z0+dz)*3136 + y0*56)*32;
            BULK(win0 + dz*PL16, gX + rowoff, PL16, mb_win);                       // s
            BULK(win1 + dz*PL16, gX + (size_t)NSITE*32 + rowoff, PL16, mb_win);    // vx
        }
        MBAR_TX(smb+8,  SLAB1); BULK(slabs,         gW,         SLAB1, smb+8);
        MBAR_TX(smb+16, SLAB1); BULK(slabs + SLAB1, gW + SLAB1, SLAB1, smb+16);
    }

    // per-warp A lane offsets (mt = w*4 + m)
    uint32_t soff[4];
    #pragma unroll
    for (int mt=0; mt<4; mt++)
        soff[mt] = (uint32_t)((w*4+mt)*16 + (l&15))*32u + ((uint32_t)(l>>4))*16u;
    const uint32_t bsw = swz(((uint32_t)((l&7)+((l&16)>>1)))*32u + ((uint32_t)(l&8)<<1));

    float acc[4][8][4];
    #pragma unroll
    for (int mt=0;mt<4;mt++)
        #pragma unroll
        for (int nt=0;nt<8;nt++)
            #pragma unroll
            for (int q=0;q<4;q++) acc[mt][nt][q] = 0.f;

    MBAR_WAIT(mb_win, 0);

    for (int i=0;i<50;i++){
        if (i==25) MBAR_WAIT(mb_win, 1);
        const int q = i&1;
        MBAR_WAIT(smb+8+q*8, (i>>1)&1);
        const uint32_t sl = slabs + q*SLAB1;
        if (i < 25){
            #pragma unroll
            for (int jt=0;jt<5;jt++){
                const int t = i*5 + jt;
                const int dz = t/25, dy = (t/5)%5, dx = t%5;
                const uint32_t D = (uint32_t)((dz*8+dy)*56 + dx)*32u;
                const uint32_t tb = sl + (uint32_t)jt*3072u + bsw;
                uint32_t b1[4], b2x[4], b2y[4], b2z[4], b4x[4], b3[4];
                LDSM_X4(b1,  tb);        LDSM_X4(b2x, tb+512);
                LDSM_X4(b2y, tb+1024);   LDSM_X4(b2z, tb+1536);
                LDSM_X4(b4x, tb+2048);   LDSM_X4(b3,  tb+2560);
                #pragma unroll
                for (int mt=0; mt<4; mt++){
                    uint32_t afS[4], afX[4];
                    LDSM_X4(afS, win0 + swz(soff[mt] + D));
                    LDSM_X4(afX, win1 + swz(soff[mt] + D));
                    MMA16816(acc[mt][0], afS, b1);    MMA16816(acc[mt][1], afS, b1+2);
                    MMA16816(acc[mt][2], afS, b2x);   MMA16816(acc[mt][3], afS, b2x+2);
                    MMA16816(acc[mt][4], afS, b2y);   MMA16816(acc[mt][5], afS, b2y+2);
                    MMA16816(acc[mt][6], afS, b2z);   MMA16816(acc[mt][7], afS, b2z+2);
                    MMA16816(acc[mt][0], afX, b4x);   MMA16816(acc[mt][1], afX, b4x+2);
                    MMA16816(acc[mt][2], afX, b3);    MMA16816(acc[mt][3], afX, b3+2);
                }
            }
        } else {
            #pragma unroll
            for (int jt=0;jt<5;jt++){
                const int t = (i-25)*5 + jt;
                const int dz = t/25, dy = (t/5)%5, dx = t%5;
                const uint32_t D = (uint32_t)((dz*8+dy)*56 + dx)*32u;
                const uint32_t tb = sl + (uint32_t)jt*1536u + bsw;
                uint32_t b4y[4], b4z[4], b3[4];
                LDSM_X4(b4y, tb); LDSM_X4(b4z, tb+512); LDSM_X4(b3, tb+1024);
                #pragma unroll
                for (int mt=0; mt<4; mt++){
                    uint32_t afY[4], afZ[4];
                    LDSM_X4(afY, win0 + swz(soff[mt] + D));
                    LDSM_X4(afZ, win1 + swz(soff[mt] + D));
                    MMA16816(acc[mt][0], afY, b4y);   MMA16816(acc[mt][1], afY, b4y+2);
                    MMA16816(acc[mt][0], afZ, b4z);   MMA16816(acc[mt][1], afZ, b4z+2);
                    MMA16816(acc[mt][4], afY, b3);    MMA16816(acc[mt][5], afY, b3+2);
                    MMA16816(acc[mt][6], afZ, b3);    MMA16816(acc[mt][7], afZ, b3+2);
                }
            }
        }
        __syncthreads();
        if (tid==0){
            const int nx = i + 2;
            if (nx < 50){
                const uint32_t bytes = (nx<25) ? SLAB1 : SLAB2;
                const size_t srcoff = (nx<25) ? (size_t)nx*SLAB1
                                              : (size_t)WPASS2 + (size_t)(nx-25)*SLAB2;
                MBAR_TX(smb+8+q*8, bytes);
                BULK(slabs + q*SLAB1, gW + srcoff, bytes, smb+8+q*8);
            }
            if (i==24){   // pass1 windows dead -> load vy, vz
                MBAR_TX(mb_win, 2u*WIN16);
                #pragma unroll
                for (int dz=0;dz<5;dz++){
                    const size_t rowoff = (size_t)((z0+dz)*3136 + y0*56)*32;
                    BULK(win0 + dz*PL16, gX + (size_t)NSITE*64 + rowoff, PL16, mb_win);
                    BULK(win1 + dz*PL16, gX + (size_t)NSITE*96 + rowoff, PL16, mb_win);
                }
            }
        }
    }

    // ---- epilogue: scatter accs to out[c][z][y][x] ----
    #pragma unroll
    for (int mt=0; mt<4; mt++){
        #pragma unroll
        for (int h=0; h<2; h++){
            const int r = (w*4+mt)*16 + (l>>2) + h*8;
            const int yy = r/56, xp = r - yy*56;
            if (yy < 4 && xp < OD){
                const size_t sp = ((size_t)z0*OD + (y0+yy))*OD + xp;
                #pragma unroll
                for (int ntp=0; ntp<8; ntp++){
                    const int nl = (ntp&1)*8 + 2*(l&3);
                    const int g = ntp>>1;
                    const int ch0 = (g==0) ? nl   : 16 + nl*3     + (g-1);
                    const int ch1 = (g==0) ? nl+1 : 16 + (nl+1)*3 + (g-1);
                    out[(size_t)ch0*OSZ + sp] = acc[mt][ntp][h*2];
                    out[(size_t)ch1*OSZ + sp] = acc[mt][ntp][h*2+1];
                }
            }
        }
    }
}

// ---------------------------------------------------------------------------
extern "C" void kernel_launch(void* const* d_in, const int* in_sizes, int n_in,
                              void* d_out, int out_size){
    const float* x      = (const float*)d_in[0];
    const float* weight = (const float*)d_in[1];
    const float* w_sc0  = (const float*)d_in[2];
    const float* w_sc1  = (const float*)d_in[3];
    float* out = (float*)d_out;

    build_w<<<125,256>>>(weight, w_sc0, w_sc1);
    dim3 gx(NSITE/512, 4);
    conv_x<<<gx,256>>>(x);

    cudaFuncSetAttribute(conv_mma, cudaFuncAttributeMaxDynamicSharedMemorySize, SMEMB);
    dim3 grid(13, 52);
    conv_mma<<<grid,128,SMEMB>>>(out);
}